// round 15
// baseline (speedup 1.0000x reference)
#include <cuda_runtime.h>
#include <cstdint>
typedef unsigned long long u64; typedef unsigned int u32;

#define NA 4096
#define HS 128
#define KSPL 4
#define CSC 0.3606737602222409f   /* 0.25*log2(e) */

__device__ float g_Qp[NA*HS], g_Kp[NA*HS], g_Vp[NA*HS];
__device__ float g_op[KSPL][NA][HS];
__device__ float g_lp[KSPL][NA][8];
__device__ float2 g_WT[4][64][128];   // [matrix][k2][j] = (W[j][2k2], W[j][2k2+1])

__device__ __forceinline__ void fma2(u64 &d, u64 a, u64 b) {
    asm("fma.rn.f32x2 %0, %1, %2, %0;" : "+l"(d) : "l"(a), "l"(b));
}
__device__ __forceinline__ float2 unpack2(u64 v) {
    float2 r; asm("mov.b64 {%0, %1}, %2;" : "=f"(r.x), "=f"(r.y) : "l"(v)); return r;
}
__device__ __forceinline__ float ex2f(float x) { float r; asm("ex2.approx.ftz.f32 %0, %1;" : "=f"(r) : "f"(x)); return r; }
__device__ __forceinline__ u32 tf32rna(float x) { u32 r; asm("cvt.rna.tf32.f32 %0, %1;" : "=r"(r) : "f"(x)); return r; }

__device__ __forceinline__ void mma8(float* d, const u32* a, u32 b0, u32 b1) {
    asm volatile("mma.sync.aligned.m16n8k8.row.col.f32.tf32.tf32.f32 "
        "{%0,%1,%2,%3},{%4,%5,%6,%7},{%8,%9},{%0,%1,%2,%3};"
        : "+f"(d[0]), "+f"(d[1]), "+f"(d[2]), "+f"(d[3])
        : "r"(a[0]), "r"(a[1]), "r"(a[2]), "r"(a[3]), "r"(b0), "r"(b1));
}

// ---------------- weight pre-transpose ----------------
__global__ __launch_bounds__(256) void wprep_kernel(
    const float* __restrict__ Wq, const float* __restrict__ Wk,
    const float* __restrict__ Wv, const float* __restrict__ Wo)
{
    __shared__ float ts[32][33];
    const int bx = blockIdx.x;
    const int m = bx >> 4, jt = (bx >> 2) & 3, kt = bx & 3;
    const float* W = (m == 0) ? Wq : (m == 1) ? Wk : (m == 2) ? Wv : Wo;
    const int tid = threadIdx.x, c = tid & 31, r8 = tid >> 5;
#pragma unroll
    for (int i = 0; i < 4; i++)
        ts[r8 + 8 * i][c] = W[(size_t)(jt * 32 + r8 + 8 * i) * HS + kt * 32 + c];
    __syncthreads();
    const int jj = tid & 31;
#pragma unroll
    for (int it = 0; it < 2; it++) {
        int kk = (tid >> 5) + 8 * it;
        g_WT[m][kt * 16 + kk][jt * 32 + jj] = make_float2(ts[jj][2 * kk], ts[jj][2 * kk + 1]);
    }
}

// ---------------- fused QKV projection ----------------
__global__ __launch_bounds__(256) void projqkv_kernel(
    const float* __restrict__ query, const float* __restrict__ key,
    const float* __restrict__ value, const float* __restrict__ bq,
    const float* __restrict__ bk, const float* __restrict__ bv)
{
    __shared__ float xs[16 * HS];
    const int which = blockIdx.x >> 8;
    const int row0 = (blockIdx.x & 255) * 16;
    const float* X = (which == 0) ? query : (which == 1) ? key : value;
    const float* b = (which == 0) ? bq : (which == 1) ? bk : bv;
    float* Y = (which == 0) ? g_Qp : (which == 1) ? g_Kp : g_Vp;

    const int tid = threadIdx.x;
    const float4* Xg = (const float4*)(X + (size_t)row0 * HS);
    float4* xs4 = (float4*)xs;
    xs4[tid] = Xg[tid]; xs4[tid + 256] = Xg[tid + 256];
    __syncthreads();
    const int j = tid & 127, rh = tid >> 7;
    u64 acc[8];
#pragma unroll
    for (int r = 0; r < 8; r++) acc[r] = 0ull;
    const u64* W2 = (const u64*)&g_WT[which][0][0];
    const u64* x2 = (const u64*)xs + rh * 8 * 64;
#pragma unroll 8
    for (int k2 = 0; k2 < 64; k2++) {
        u64 wv = W2[k2 * 128 + j];
#pragma unroll
        for (int r = 0; r < 8; r++) fma2(acc[r], x2[r * 64 + k2], wv);
    }
    const float bj = b[j];
#pragma unroll
    for (int r = 0; r < 8; r++) {
        float2 a = unpack2(acc[r]);
        Y[(size_t)(row0 + rh * 8 + r) * HS + j] = a.x + a.y + bj;
    }
}

// ------- fused reduce (4 splits) + output projection: 8-row tiles, 512 CTAs --
__global__ __launch_bounds__(256) void projo_kernel(float* __restrict__ out)
{
    __shared__ float xs[8 * HS];
    __shared__ float ls[8][8];
    const int tid = threadIdx.x, row0 = blockIdx.x * 8;

    float4 s;
    const int r = tid >> 5, c = tid & 31;
    {
        float4 a0 = *(const float4*)&g_op[0][row0 + r][c * 4];
        float4 a1 = *(const float4*)&g_op[1][row0 + r][c * 4];
        float4 a2 = *(const float4*)&g_op[2][row0 + r][c * 4];
        float4 a3 = *(const float4*)&g_op[3][row0 + r][c * 4];
        s = make_float4(a0.x + a1.x + a2.x + a3.x, a0.y + a1.y + a2.y + a3.y,
                        a0.z + a1.z + a2.z + a3.z, a0.w + a1.w + a2.w + a3.w);
    }
    if (tid < 64) {
        int rr = tid >> 3, h = tid & 7;
        ls[rr][h] = g_lp[0][row0 + rr][h] + g_lp[1][row0 + rr][h]
                  + g_lp[2][row0 + rr][h] + g_lp[3][row0 + rr][h];
    }
    __syncthreads();
    {
        float inv = 1.0f / ls[r][c >> 2];
        ((float4*)xs)[tid] = make_float4(s.x * inv, s.y * inv, s.z * inv, s.w * inv);
    }
    __syncthreads();
    const int j = tid & 127, rh = tid >> 7;
    u64 acc[4];
#pragma unroll
    for (int q = 0; q < 4; q++) acc[q] = 0ull;
    const u64* W2 = (const u64*)&g_WT[3][0][0];
    const u64* x2 = (const u64*)xs + rh * 4 * 64;
#pragma unroll 8
    for (int k2 = 0; k2 < 64; k2++) {
        u64 wv = W2[k2 * 128 + j];
#pragma unroll
        for (int q = 0; q < 4; q++) fma2(acc[q], x2[q * 64 + k2], wv);
    }
#pragma unroll
    for (int q = 0; q < 4; q++) {
        float2 a = unpack2(acc[q]);
        out[(size_t)(row0 + rh * 4 + q) * HS + j] = a.x + a.y;
    }
}

// ------- mma.sync tf32 flash attention: 1024 thr, 32 warps, 16 q/warp --------
// warp = (head h, q-group qg); warps 0-15 stage K+mask, warps 16-31 stage V.
// grid = 64 q-tiles x 4 key-splits = 256 CTAs; 64 q/CTA; 8 warps/SMSP.
#define KST 132
#define VST 136
#define NTIL (1024 / 16)
__global__ __launch_bounds__(1024, 1) void attn_kernel(const int* __restrict__ mask)
{
    __shared__ float ksm[2][16 * KST];
    __shared__ float vsm[2][16 * VST];
    __shared__ u32 msm[2][64];
    const int tid = threadIdx.x, lane = tid & 31, w = tid >> 5;
    const int h = w & 7, qg = (w >> 3) & 3;
    const int qt = blockIdx.x >> 2, ks = blockIdx.x & 3;
    const int q0 = qt * 64, K0 = ks * 1024;
    const int gid = lane >> 2, tig = lane & 3;

    u32 qf[2][4];
    {
        const float* Qb = g_Qp + (size_t)(q0 + qg * 16) * HS + h * 16;
#pragma unroll
        for (int kk = 0; kk < 2; kk++) {
            int c0 = kk * 8 + tig;
            qf[kk][0] = tf32rna(Qb[(size_t)gid * HS + c0] * CSC);
            qf[kk][1] = tf32rna(Qb[(size_t)(gid + 8) * HS + c0] * CSC);
            qf[kk][2] = tf32rna(Qb[(size_t)gid * HS + c0 + 4] * CSC);
            qf[kk][3] = tf32rna(Qb[(size_t)(gid + 8) * HS + c0 + 4] * CSC);
        }
    }
    float of[2][4];
    float l0 = 0.0f, l1 = 0.0f;
#pragma unroll
    for (int ns = 0; ns < 2; ns++)
#pragma unroll
        for (int c = 0; c < 4; c++) of[ns][c] = 0.0f;

    // staging: warps 0-15 (stv=0) stage K + mask; warps 16-31 stage V
    const int stv = w >> 4;
    const int sid = tid & 511;
    const int skey = sid >> 5, c4 = sid & 31;
    const int krow = (skey & 8) | ((skey & 3) << 1) | ((skey >> 2) & 1);   // perm
    const int mq = sid >> 3, mk = sid & 7;

    float4 pre; int2 mpre;
    if (!stv) {
        pre = *(const float4*)(g_Kp + (size_t)(K0 + skey) * HS + 4 * c4);
        mpre = *(const int2*)(mask + (size_t)(q0 + mq) * NA + K0 + 2 * mk);
    } else {
        pre = *(const float4*)(g_Vp + (size_t)(K0 + skey) * HS + 4 * c4);
    }

    for (int t = 0; t < NTIL; t++) {
        const int buf = t & 1;
        {
            u32 cc[4]; float vv[4];
            *(float4*)vv = pre;
#pragma unroll
            for (int i = 0; i < 4; i++) cc[i] = tf32rna(vv[i]);
            if (!stv) {
                *(float4*)(ksm[buf] + krow * KST + 4 * c4) = *(float4*)cc;
                u32 bm = ((mpre.x ? 1u : 0u) | (mpre.y ? 2u : 0u)) << (2 * mk);
                bm |= __shfl_xor_sync(0xffffffffu, bm, 1);
                bm |= __shfl_xor_sync(0xffffffffu, bm, 2);
                bm |= __shfl_xor_sync(0xffffffffu, bm, 4);
                if (mk == 0) msm[buf][mq] = bm;
            } else {
                *(float4*)(vsm[buf] + skey * VST + 4 * c4) = *(float4*)cc;
            }
        }
        __syncthreads();   // one barrier per tile (double buffer covers WAR)
        if (t + 1 < NTIL) {
            const int kbase = K0 + (t + 1) * 16;
            if (!stv) {
                pre = *(const float4*)(g_Kp + (size_t)(kbase + skey) * HS + 4 * c4);
                mpre = *(const int2*)(mask + (size_t)(q0 + mq) * NA + kbase + 2 * mk);
            } else {
                pre = *(const float4*)(g_Vp + (size_t)(kbase + skey) * HS + 4 * c4);
            }
        }
        const float* kb = ksm[buf];
        const float* vs = vsm[buf];

        // S = Q K^T (permuted key positions): 4 MMAs
        float sf[2][4];
#pragma unroll
        for (int nt = 0; nt < 2; nt++)
#pragma unroll
            for (int c = 0; c < 4; c++) sf[nt][c] = 0.0f;
#pragma unroll
        for (int nt = 0; nt < 2; nt++)
#pragma unroll
            for (int kk = 0; kk < 2; kk++) {
                u32 b0 = __float_as_uint(kb[(nt * 8 + gid) * KST + h * 16 + kk * 8 + tig]);
                u32 b1 = __float_as_uint(kb[(nt * 8 + gid) * KST + h * 16 + kk * 8 + tig + 4]);
                mma8(sf[nt], qf[kk], b0, b1);
            }

        // epilogue: P tf32-truncated via AND; l on fma pipe; PV: 4 MMAs
        const u32 w0 = msm[buf][qg * 16 + gid];
        const u32 w1 = msm[buf][qg * 16 + gid + 8];
#pragma unroll
        for (int nt = 0; nt < 2; nt++) {
            int c0 = nt * 8 + tig;
            u32 a[4];
            a[0] = ((w0 >> c0) & 1u)       ? (__float_as_uint(ex2f(sf[nt][0])) & 0xFFFFE000u) : 0u;
            a[2] = ((w0 >> (c0 + 4)) & 1u) ? (__float_as_uint(ex2f(sf[nt][1])) & 0xFFFFE000u) : 0u;
            a[1] = ((w1 >> c0) & 1u)       ? (__float_as_uint(ex2f(sf[nt][2])) & 0xFFFFE000u) : 0u;
            a[3] = ((w1 >> (c0 + 4)) & 1u) ? (__float_as_uint(ex2f(sf[nt][3])) & 0xFFFFE000u) : 0u;
            l0 += __uint_as_float(a[0]) + __uint_as_float(a[2]);
            l1 += __uint_as_float(a[1]) + __uint_as_float(a[3]);
#pragma unroll
            for (int ns = 0; ns < 2; ns++) {
                u32 vb0 = __float_as_uint(vs[(nt * 8 + tig) * VST + h * 16 + ns * 8 + gid]);
                u32 vb1 = __float_as_uint(vs[(nt * 8 + tig + 4) * VST + h * 16 + ns * 8 + gid]);
                mma8(of[ns], a, vb0, vb1);
            }
        }
    }

    {
        const int q = q0 + qg * 16 + gid;
#pragma unroll
        for (int ns = 0; ns < 2; ns++) {
            int d = h * 16 + ns * 8 + 2 * tig;
            *(float2*)&g_op[ks][q][d]     = make_float2(of[ns][0], of[ns][1]);
            *(float2*)&g_op[ks][q + 8][d] = make_float2(of[ns][2], of[ns][3]);
        }
        float v0 = l0;
        v0 += __shfl_xor_sync(0xffffffffu, v0, 1);
        v0 += __shfl_xor_sync(0xffffffffu, v0, 2);
        float v1 = l1;
        v1 += __shfl_xor_sync(0xffffffffu, v1, 1);
        v1 += __shfl_xor_sync(0xffffffffu, v1, 2);
        if (tig == 0) {
            g_lp[ks][q][h]     = v0;
            g_lp[ks][q + 8][h] = v1;
        }
    }
}

// ============================================================================
extern "C" void kernel_launch(void* const* d_in, const int* in_sizes, int n_in,
                              void* d_out, int out_size)
{
    const float* query = (const float*)d_in[0];
    const float* key   = (const float*)d_in[1];
    const float* value = (const float*)d_in[2];
    const int*   mask  = (const int*)  d_in[3];
    const float* Wq = (const float*)d_in[4];  const float* bq = (const float*)d_in[5];
    const float* Wk = (const float*)d_in[6];  const float* bk = (const float*)d_in[7];
    const float* Wv = (const float*)d_in[8];  const float* bv = (const float*)d_in[9];
    const float* Wo = (const float*)d_in[10];
    float* out = (float*)d_out;

    wprep_kernel<<<64, 256>>>(Wq, Wk, Wv, Wo);
    projqkv_kernel<<<768, 256>>>(query, key, value, bq, bk, bv);
    attn_kernel<<<256, 1024>>>(mask);
    projo_kernel<<<512, 256>>>(out);
}

// round 16
// speedup vs baseline: 1.3063x; 1.3063x over previous
#include <cuda_runtime.h>
#include <cstdint>
typedef unsigned long long u64; typedef unsigned int u32;

#define NA 4096
#define HS 128
#define KSPL 4
#define CSC 0.3606737602222409f   /* 0.25*log2(e) */

__device__ float g_Qp[NA*HS], g_Kp[NA*HS], g_Vp[NA*HS];
__device__ float g_op[KSPL][NA][HS];
__device__ float g_lp[KSPL][NA][8];
__device__ float2 g_WT[4][64][128];   // [matrix][k2][j] = (W[j][2k2], W[j][2k2+1])

__device__ __forceinline__ void fma2(u64 &d, u64 a, u64 b) {
    asm("fma.rn.f32x2 %0, %1, %2, %0;" : "+l"(d) : "l"(a), "l"(b));
}
__device__ __forceinline__ float2 unpack2(u64 v) {
    float2 r; asm("mov.b64 {%0, %1}, %2;" : "=f"(r.x), "=f"(r.y) : "l"(v)); return r;
}
__device__ __forceinline__ float ex2f(float x) { float r; asm("ex2.approx.ftz.f32 %0, %1;" : "=f"(r) : "f"(x)); return r; }
__device__ __forceinline__ u32 tf32rna(float x) { u32 r; asm("cvt.rna.tf32.f32 %0, %1;" : "=r"(r) : "f"(x)); return r; }

__device__ __forceinline__ void mma8(float* d, const u32* a, u32 b0, u32 b1) {
    asm volatile("mma.sync.aligned.m16n8k8.row.col.f32.tf32.tf32.f32 "
        "{%0,%1,%2,%3},{%4,%5,%6,%7},{%8,%9},{%0,%1,%2,%3};"
        : "+f"(d[0]), "+f"(d[1]), "+f"(d[2]), "+f"(d[3])
        : "r"(a[0]), "r"(a[1]), "r"(a[2]), "r"(a[3]), "r"(b0), "r"(b1));
}

// ---------------- weight pre-transpose ----------------
__global__ __launch_bounds__(256) void wprep_kernel(
    const float* __restrict__ Wq, const float* __restrict__ Wk,
    const float* __restrict__ Wv, const float* __restrict__ Wo)
{
    __shared__ float ts[32][33];
    const int bx = blockIdx.x;
    const int m = bx >> 4, jt = (bx >> 2) & 3, kt = bx & 3;
    const float* W = (m == 0) ? Wq : (m == 1) ? Wk : (m == 2) ? Wv : Wo;
    const int tid = threadIdx.x, c = tid & 31, r8 = tid >> 5;
#pragma unroll
    for (int i = 0; i < 4; i++)
        ts[r8 + 8 * i][c] = W[(size_t)(jt * 32 + r8 + 8 * i) * HS + kt * 32 + c];
    __syncthreads();
    const int jj = tid & 31;
#pragma unroll
    for (int it = 0; it < 2; it++) {
        int kk = (tid >> 5) + 8 * it;
        g_WT[m][kt * 16 + kk][jt * 32 + jj] = make_float2(ts[jj][2 * kk], ts[jj][2 * kk + 1]);
    }
}

// ---------------- fused QKV projection (unroll 16 on the L2-hot W stream) ----
__global__ __launch_bounds__(256) void projqkv_kernel(
    const float* __restrict__ query, const float* __restrict__ key,
    const float* __restrict__ value, const float* __restrict__ bq,
    const float* __restrict__ bk, const float* __restrict__ bv)
{
    __shared__ float xs[16 * HS];
    const int which = blockIdx.x >> 8;
    const int row0 = (blockIdx.x & 255) * 16;
    const float* X = (which == 0) ? query : (which == 1) ? key : value;
    const float* b = (which == 0) ? bq : (which == 1) ? bk : bv;
    float* Y = (which == 0) ? g_Qp : (which == 1) ? g_Kp : g_Vp;

    const int tid = threadIdx.x;
    const float4* Xg = (const float4*)(X + (size_t)row0 * HS);
    float4* xs4 = (float4*)xs;
    xs4[tid] = Xg[tid]; xs4[tid + 256] = Xg[tid + 256];
    __syncthreads();
    const int j = tid & 127, rh = tid >> 7;
    u64 acc[8];
#pragma unroll
    for (int r = 0; r < 8; r++) acc[r] = 0ull;
    const u64* W2 = (const u64*)&g_WT[which][0][0];
    const u64* x2 = (const u64*)xs + rh * 8 * 64;
#pragma unroll 16
    for (int k2 = 0; k2 < 64; k2++) {
        u64 wv = W2[k2 * 128 + j];
#pragma unroll
        for (int r = 0; r < 8; r++) fma2(acc[r], x2[r * 64 + k2], wv);
    }
    const float bj = b[j];
#pragma unroll
    for (int r = 0; r < 8; r++) {
        float2 a = unpack2(acc[r]);
        Y[(size_t)(row0 + rh * 8 + r) * HS + j] = a.x + a.y + bj;
    }
}

// ------- fused reduce (4 splits) + output projection (unroll 16) -------------
__global__ __launch_bounds__(256) void projo_kernel(float* __restrict__ out)
{
    __shared__ float xs[8 * HS];
    __shared__ float ls[8][8];
    const int tid = threadIdx.x, row0 = blockIdx.x * 8;

    float4 s;
    const int r = tid >> 5, c = tid & 31;
    {
        float4 a0 = *(const float4*)&g_op[0][row0 + r][c * 4];
        float4 a1 = *(const float4*)&g_op[1][row0 + r][c * 4];
        float4 a2 = *(const float4*)&g_op[2][row0 + r][c * 4];
        float4 a3 = *(const float4*)&g_op[3][row0 + r][c * 4];
        s = make_float4(a0.x + a1.x + a2.x + a3.x, a0.y + a1.y + a2.y + a3.y,
                        a0.z + a1.z + a2.z + a3.z, a0.w + a1.w + a2.w + a3.w);
    }
    if (tid < 64) {
        int rr = tid >> 3, h = tid & 7;
        ls[rr][h] = g_lp[0][row0 + rr][h] + g_lp[1][row0 + rr][h]
                  + g_lp[2][row0 + rr][h] + g_lp[3][row0 + rr][h];
    }
    __syncthreads();
    {
        float inv = 1.0f / ls[r][c >> 2];
        ((float4*)xs)[tid] = make_float4(s.x * inv, s.y * inv, s.z * inv, s.w * inv);
    }
    __syncthreads();
    const int j = tid & 127, rh = tid >> 7;
    u64 acc[4];
#pragma unroll
    for (int q = 0; q < 4; q++) acc[q] = 0ull;
    const u64* W2 = (const u64*)&g_WT[3][0][0];
    const u64* x2 = (const u64*)xs + rh * 4 * 64;
#pragma unroll 16
    for (int k2 = 0; k2 < 64; k2++) {
        u64 wv = W2[k2 * 128 + j];
#pragma unroll
        for (int q = 0; q < 4; q++) fma2(acc[q], x2[q * 64 + k2], wv);
    }
#pragma unroll
    for (int q = 0; q < 4; q++) {
        float2 a = unpack2(acc[q]);
        out[(size_t)(row0 + rh * 4 + q) * HS + j] = a.x + a.y;
    }
}

// ------- mma.sync tf32 flash attention (round-12 best-known shape) -----------
// 512 thr = 16 warps = 8 heads x 2 q-halves; 64 q/CTA; grid = 64x4 = 256 CTAs.
// P truncated to tf32 via AND-mask; l on fma pipe; permuted-K (shuffle-free).
#define KST 132
#define VST 136
#define NTIL (1024 / 16)
__global__ __launch_bounds__(512, 1) void attn_kernel(const int* __restrict__ mask)
{
    __shared__ float ksm[2][16 * KST];
    __shared__ float vsm[2][16 * VST];
    __shared__ u32 msm[2][64];
    const int tid = threadIdx.x, lane = tid & 31, w = tid >> 5;
    const int h = w >> 1, half = w & 1;
    const int qt = blockIdx.x >> 2, ks = blockIdx.x & 3;
    const int q0 = qt * 64, K0 = ks * 1024;
    const int gid = lane >> 2, tig = lane & 3;

    u32 qf[2][2][4];
    {
        const float* Qb = g_Qp + (size_t)(q0 + half * 32) * HS + h * 16;
#pragma unroll
        for (int mt = 0; mt < 2; mt++)
#pragma unroll
            for (int kk = 0; kk < 2; kk++) {
                int r0 = mt * 16 + gid, c0 = kk * 8 + tig;
                qf[mt][kk][0] = tf32rna(Qb[(size_t)r0 * HS + c0] * CSC);
                qf[mt][kk][1] = tf32rna(Qb[(size_t)(r0 + 8) * HS + c0] * CSC);
                qf[mt][kk][2] = tf32rna(Qb[(size_t)r0 * HS + c0 + 4] * CSC);
                qf[mt][kk][3] = tf32rna(Qb[(size_t)(r0 + 8) * HS + c0 + 4] * CSC);
            }
    }
    float of[2][2][4];
    float l0[2], l1[2];
#pragma unroll
    for (int a = 0; a < 2; a++) {
        l0[a] = 0.0f; l1[a] = 0.0f;
#pragma unroll
        for (int b2 = 0; b2 < 2; b2++)
#pragma unroll
            for (int c = 0; c < 4; c++) of[a][b2][c] = 0.0f;
    }

    const int pk = tid >> 5, pd = tid & 31;
    const int krow = (pk & 8) | ((pk & 3) << 1) | ((pk >> 2) & 1);   // permuted key pos
    const int mq = tid >> 3, mk = tid & 7;

    float4 kpre, vpre; int2 mpre;
    kpre = *(const float4*)(g_Kp + (size_t)(K0 + pk) * HS + 4 * pd);
    vpre = *(const float4*)(g_Vp + (size_t)(K0 + pk) * HS + 4 * pd);
    mpre = *(const int2*)(mask + (size_t)(q0 + mq) * NA + K0 + 2 * mk);

    for (int t = 0; t < NTIL; t++) {
        const int buf = t & 1;
        {
            u32 kc[4], vc[4]; float kv[4], vv[4];
            *(float4*)kv = kpre; *(float4*)vv = vpre;
#pragma unroll
            for (int i = 0; i < 4; i++) { kc[i] = tf32rna(kv[i]); vc[i] = tf32rna(vv[i]); }
            *(float4*)(ksm[buf] + krow * KST + 4 * pd) = *(float4*)kc;
            *(float4*)(vsm[buf] + pk * VST + 4 * pd) = *(float4*)vc;
            u32 bm = ((mpre.x ? 1u : 0u) | (mpre.y ? 2u : 0u)) << (2 * mk);
            bm |= __shfl_xor_sync(0xffffffffu, bm, 1);
            bm |= __shfl_xor_sync(0xffffffffu, bm, 2);
            bm |= __shfl_xor_sync(0xffffffffu, bm, 4);
            if (mk == 0) msm[buf][mq] = bm;
        }
        __syncthreads();   // single barrier per tile (double buffer covers WAR)
        if (t + 1 < NTIL) {
            kpre = *(const float4*)(g_Kp + (size_t)(K0 + (t + 1) * 16 + pk) * HS + 4 * pd);
            vpre = *(const float4*)(g_Vp + (size_t)(K0 + (t + 1) * 16 + pk) * HS + 4 * pd);
            mpre = *(const int2*)(mask + (size_t)(q0 + mq) * NA + K0 + (t + 1) * 16 + 2 * mk);
        }
        const float* kb = ksm[buf];
        const float* vs = vsm[buf];

        u32 vb[2][2][2];
#pragma unroll
        for (int nt = 0; nt < 2; nt++)
#pragma unroll
            for (int ns = 0; ns < 2; ns++) {
                vb[nt][ns][0] = __float_as_uint(vs[(nt * 8 + tig) * VST + h * 16 + ns * 8 + gid]);
                vb[nt][ns][1] = __float_as_uint(vs[(nt * 8 + tig + 4) * VST + h * 16 + ns * 8 + gid]);
            }

        float sf[2][2][4];
#pragma unroll
        for (int mt = 0; mt < 2; mt++)
#pragma unroll
            for (int nt = 0; nt < 2; nt++)
#pragma unroll
                for (int c = 0; c < 4; c++) sf[mt][nt][c] = 0.0f;
#pragma unroll
        for (int nt = 0; nt < 2; nt++)
#pragma unroll
            for (int kk = 0; kk < 2; kk++) {
                u32 b0 = __float_as_uint(kb[(nt * 8 + gid) * KST + h * 16 + kk * 8 + tig]);
                u32 b1 = __float_as_uint(kb[(nt * 8 + gid) * KST + h * 16 + kk * 8 + tig + 4]);
#pragma unroll
                for (int mt = 0; mt < 2; mt++) mma8(sf[mt][nt], qf[mt][kk], b0, b1);
            }

        // epilogue: P tf32-truncated via AND; l accumulated on fma pipe
#pragma unroll
        for (int mt = 0; mt < 2; mt++) {
            u32 w0 = msm[buf][half * 32 + mt * 16 + gid];
            u32 w1 = msm[buf][half * 32 + mt * 16 + gid + 8];
#pragma unroll
            for (int nt = 0; nt < 2; nt++) {
                int c0 = nt * 8 + tig;
                u32 a[4];
                a[0] = ((w0 >> c0) & 1u)       ? (__float_as_uint(ex2f(sf[mt][nt][0])) & 0xFFFFE000u) : 0u;
                a[2] = ((w0 >> (c0 + 4)) & 1u) ? (__float_as_uint(ex2f(sf[mt][nt][1])) & 0xFFFFE000u) : 0u;
                a[1] = ((w1 >> c0) & 1u)       ? (__float_as_uint(ex2f(sf[mt][nt][2])) & 0xFFFFE000u) : 0u;
                a[3] = ((w1 >> (c0 + 4)) & 1u) ? (__float_as_uint(ex2f(sf[mt][nt][3])) & 0xFFFFE000u) : 0u;
                l0[mt] += __uint_as_float(a[0]) + __uint_as_float(a[2]);
                l1[mt] += __uint_as_float(a[1]) + __uint_as_float(a[3]);
#pragma unroll
                for (int ns = 0; ns < 2; ns++) mma8(of[mt][ns], a, vb[nt][ns][0], vb[nt][ns][1]);
            }
        }
    }

#pragma unroll
    for (int mt = 0; mt < 2; mt++) {
        int q = q0 + half * 32 + mt * 16 + gid;
#pragma unroll
        for (int ns = 0; ns < 2; ns++) {
            int d = h * 16 + ns * 8 + 2 * tig;
            *(float2*)&g_op[ks][q][d]     = make_float2(of[mt][ns][0], of[mt][ns][1]);
            *(float2*)&g_op[ks][q + 8][d] = make_float2(of[mt][ns][2], of[mt][ns][3]);
        }
        float v0 = l0[mt];
        v0 += __shfl_xor_sync(0xffffffffu, v0, 1);
        v0 += __shfl_xor_sync(0xffffffffu, v0, 2);
        float v1 = l1[mt];
        v1 += __shfl_xor_sync(0xffffffffu, v1, 1);
        v1 += __shfl_xor_sync(0xffffffffu, v1, 2);
        if (tig == 0) {
            g_lp[ks][q][h]     = v0;
            g_lp[ks][q + 8][h] = v1;
        }
    }
}

// ============================================================================
extern "C" void kernel_launch(void* const* d_in, const int* in_sizes, int n_in,
                              void* d_out, int out_size)
{
    const float* query = (const float*)d_in[0];
    const float* key   = (const float*)d_in[1];
    const float* value = (const float*)d_in[2];
    const int*   mask  = (const int*)  d_in[3];
    const float* Wq = (const float*)d_in[4];  const float* bq = (const float*)d_in[5];
    const float* Wk = (const float*)d_in[6];  const float* bk = (const float*)d_in[7];
    const float* Wv = (const float*)d_in[8];  const float* bv = (const float*)d_in[9];
    const float* Wo = (const float*)d_in[10];
    float* out = (float*)d_out;

    wprep_kernel<<<64, 256>>>(Wq, Wk, Wv, Wo);
    projqkv_kernel<<<768, 256>>>(query, key, value, bq, bk, bv);
    attn_kernel<<<256, 512>>>(mask);
    projo_kernel<<<512, 256>>>(out);
}